// round 4
// baseline (speedup 1.0000x reference)
#include <cuda_runtime.h>

// Problem dims (fixed by the reference)
#define T_DIM 64
#define B_DIM 1024
#define N_DIM 512
#define M_DIM (T_DIM * B_DIM)   // 65536
#define K_DIM 512

// Scratch (allocation-free: __device__ globals)
__device__ float g_h[(size_t)M_DIM * N_DIM];   // fc1 output  (134 MB)
__device__ float g_s[(size_t)M_DIM * N_DIM];   // spikes      (134 MB)

// ----------------------------------------------------------------------------
// SGEMM (NT): C[m][n] = sum_k A[m][k] * W[n][k] + bias[n]
//   A: [M,K] row-major (K contiguous), W: [N,K] row-major (K contiguous)
// Block tile 128x128, K-tile 8, 256 threads, 8x8 per thread.
// All dims compile-time constants -> fully unrolled addressing.
// ----------------------------------------------------------------------------
#define BM 128
#define BN 128
#define BK 8
#define TM 8
#define TN 8

__global__ __launch_bounds__(256, 2) void sgemm_nt(
    const float* __restrict__ A,
    const float* __restrict__ W,
    const float* __restrict__ bias,
    float* __restrict__ C)
{
    __shared__ float As[BK][BM];
    __shared__ float Bs[BK][BN];

    const int tid = threadIdx.x;
    const int bm = blockIdx.y * BM;
    const int bn = blockIdx.x * BN;

    // Loader mapping: 256 threads x 1 float4 = 1024 floats = one 128x8 tile
    const int lrow = tid >> 1;          // 0..127
    const int lcol = (tid & 1) * 4;     // 0 or 4

    // Compute mapping: 16x16 threads of 8x8 micro-tiles
    const int tr = (tid >> 4) * TM;     // 0,8,...,120
    const int tc = (tid & 15) * TN;     // 0,8,...,120

    float acc[TM][TN];
    #pragma unroll
    for (int i = 0; i < TM; i++)
        #pragma unroll
        for (int j = 0; j < TN; j++)
            acc[i][j] = 0.0f;

    const float* Aptr = A + (size_t)(bm + lrow) * K_DIM + lcol;
    const float* Wptr = W + (size_t)(bn + lrow) * K_DIM + lcol;

    for (int k0 = 0; k0 < K_DIM; k0 += BK) {
        float4 av = *reinterpret_cast<const float4*>(Aptr + k0);
        float4 wv = *reinterpret_cast<const float4*>(Wptr + k0);
        As[lcol + 0][lrow] = av.x;
        As[lcol + 1][lrow] = av.y;
        As[lcol + 2][lrow] = av.z;
        As[lcol + 3][lrow] = av.w;
        Bs[lcol + 0][lrow] = wv.x;
        Bs[lcol + 1][lrow] = wv.y;
        Bs[lcol + 2][lrow] = wv.z;
        Bs[lcol + 3][lrow] = wv.w;
        __syncthreads();

        #pragma unroll
        for (int k = 0; k < BK; k++) {
            float ra[TM], rb[TN];
            #pragma unroll
            for (int i = 0; i < TM; i += 4) {
                float4 v = *reinterpret_cast<const float4*>(&As[k][tr + i]);
                ra[i + 0] = v.x; ra[i + 1] = v.y; ra[i + 2] = v.z; ra[i + 3] = v.w;
            }
            #pragma unroll
            for (int j = 0; j < TN; j += 4) {
                float4 v = *reinterpret_cast<const float4*>(&Bs[k][tc + j]);
                rb[j + 0] = v.x; rb[j + 1] = v.y; rb[j + 2] = v.z; rb[j + 3] = v.w;
            }
            #pragma unroll
            for (int i = 0; i < TM; i++)
                #pragma unroll
                for (int j = 0; j < TN; j++)
                    acc[i][j] = fmaf(ra[i], rb[j], acc[i][j]);
        }
        __syncthreads();
    }

    // Epilogue: add bias, vectorized store
    #pragma unroll
    for (int i = 0; i < TM; i++) {
        float* Crow = C + (size_t)(bm + tr + i) * N_DIM + (bn + tc);
        #pragma unroll
        for (int j = 0; j < TN; j += 4) {
            float4 v;
            v.x = acc[i][j + 0] + bias[bn + tc + j + 0];
            v.y = acc[i][j + 1] + bias[bn + tc + j + 1];
            v.z = acc[i][j + 2] + bias[bn + tc + j + 2];
            v.w = acc[i][j + 3] + bias[bn + tc + j + 3];
            *reinterpret_cast<float4*>(Crow + j) = v;
        }
    }
}

// ----------------------------------------------------------------------------
// LIF multistep: one thread per (b, n) state; loops over T.
// charge: v = v + (h - v) * 0.5   (exact: *0.5 is power of two)
// fire:   spike = (v >= 1.0)
// reset:  hard reset to 0
// ----------------------------------------------------------------------------
__global__ __launch_bounds__(256) void lif_kernel(
    const float* __restrict__ h,
    float* __restrict__ s)
{
    const int idx = blockIdx.x * blockDim.x + threadIdx.x;  // over B*N
    const int stride = B_DIM * N_DIM;
    if (idx >= stride) return;

    float v = 0.0f;
    #pragma unroll
    for (int t = 0; t < T_DIM; t++) {
        float ht = h[(size_t)t * stride + idx];
        v = v + (ht - v) * 0.5f;
        bool fired = (v >= 1.0f);
        s[(size_t)t * stride + idx] = fired ? 1.0f : 0.0f;
        if (fired) v = 0.0f;
    }
}

// ----------------------------------------------------------------------------
// Launch
// ----------------------------------------------------------------------------
extern "C" void kernel_launch(void* const* d_in, const int* in_sizes, int n_in,
                              void* d_out, int out_size)
{
    const float* x  = (const float*)d_in[0];
    const float* w1 = (const float*)d_in[1];
    const float* b1 = (const float*)d_in[2];
    const float* w2 = (const float*)d_in[3];
    const float* b2 = (const float*)d_in[4];
    float* out = (float*)d_out;

    float* h_ptr = nullptr;
    float* s_ptr = nullptr;
    cudaGetSymbolAddress((void**)&h_ptr, g_h);
    cudaGetSymbolAddress((void**)&s_ptr, g_s);

    dim3 grid(N_DIM / BN, M_DIM / BM);   // (4, 512)
    dim3 block(256);

    // fc1: h = x @ w1^T + b1
    sgemm_nt<<<grid, block>>>(x, w1, b1, h_ptr);

    // LIF scan over T
    lif_kernel<<<(B_DIM * N_DIM) / 256, 256>>>(h_ptr, s_ptr);

    // fc2: out = s @ w2^T + b2
    sgemm_nt<<<grid, block>>>(s_ptr, w2, b2, out);
}

// round 5
// speedup vs baseline: 1.0020x; 1.0020x over previous
#include <cuda_runtime.h>

// Problem dims (fixed by the reference)
#define T_DIM 64
#define B_DIM 1024
#define N_DIM 512
#define M_DIM (T_DIM * B_DIM)   // 65536
#define K_DIM 512

// Scratch (allocation-free: __device__ globals)
__device__ float g_h[(size_t)M_DIM * N_DIM];   // fc1 output  (134 MB)
__device__ float g_s[(size_t)M_DIM * N_DIM];   // spikes      (134 MB)

// ----------------------------------------------------------------------------
// SGEMM (NT): C[m][n] = sum_k A[m][k] * W[n][k] + bias[n]
//   A: [M,K] row-major (K contiguous), W: [N,K] row-major (K contiguous)
// Block tile 128x128, K-tile 8, 256 threads, 8x8 per thread.
// All dims compile-time constants -> fully unrolled addressing.
// ----------------------------------------------------------------------------
#define BM 128
#define BN 128
#define BK 8
#define TM 8
#define TN 8

__global__ __launch_bounds__(256, 2) void sgemm_nt(
    const float* __restrict__ A,
    const float* __restrict__ W,
    const float* __restrict__ bias,
    float* __restrict__ C)
{
    __shared__ float As[BK][BM];
    __shared__ float Bs[BK][BN];

    const int tid = threadIdx.x;
    const int bm = blockIdx.y * BM;
    const int bn = blockIdx.x * BN;

    // Loader mapping: 256 threads x 1 float4 = 1024 floats = one 128x8 tile
    const int lrow = tid >> 1;          // 0..127
    const int lcol = (tid & 1) * 4;     // 0 or 4

    // Compute mapping: 16x16 threads of 8x8 micro-tiles
    const int tr = (tid >> 4) * TM;     // 0,8,...,120
    const int tc = (tid & 15) * TN;     // 0,8,...,120

    float acc[TM][TN];
    #pragma unroll
    for (int i = 0; i < TM; i++)
        #pragma unroll
        for (int j = 0; j < TN; j++)
            acc[i][j] = 0.0f;

    const float* Aptr = A + (size_t)(bm + lrow) * K_DIM + lcol;
    const float* Wptr = W + (size_t)(bn + lrow) * K_DIM + lcol;

    for (int k0 = 0; k0 < K_DIM; k0 += BK) {
        float4 av = *reinterpret_cast<const float4*>(Aptr + k0);
        float4 wv = *reinterpret_cast<const float4*>(Wptr + k0);
        As[lcol + 0][lrow] = av.x;
        As[lcol + 1][lrow] = av.y;
        As[lcol + 2][lrow] = av.z;
        As[lcol + 3][lrow] = av.w;
        Bs[lcol + 0][lrow] = wv.x;
        Bs[lcol + 1][lrow] = wv.y;
        Bs[lcol + 2][lrow] = wv.z;
        Bs[lcol + 3][lrow] = wv.w;
        __syncthreads();

        #pragma unroll
        for (int k = 0; k < BK; k++) {
            float ra[TM], rb[TN];
            #pragma unroll
            for (int i = 0; i < TM; i += 4) {
                float4 v = *reinterpret_cast<const float4*>(&As[k][tr + i]);
                ra[i + 0] = v.x; ra[i + 1] = v.y; ra[i + 2] = v.z; ra[i + 3] = v.w;
            }
            #pragma unroll
            for (int j = 0; j < TN; j += 4) {
                float4 v = *reinterpret_cast<const float4*>(&Bs[k][tc + j]);
                rb[j + 0] = v.x; rb[j + 1] = v.y; rb[j + 2] = v.z; rb[j + 3] = v.w;
            }
            #pragma unroll
            for (int i = 0; i < TM; i++)
                #pragma unroll
                for (int j = 0; j < TN; j++)
                    acc[i][j] = fmaf(ra[i], rb[j], acc[i][j]);
        }
        __syncthreads();
    }

    // Epilogue: add bias, vectorized store
    #pragma unroll
    for (int i = 0; i < TM; i++) {
        float* Crow = C + (size_t)(bm + tr + i) * N_DIM + (bn + tc);
        #pragma unroll
        for (int j = 0; j < TN; j += 4) {
            float4 v;
            v.x = acc[i][j + 0] + bias[bn + tc + j + 0];
            v.y = acc[i][j + 1] + bias[bn + tc + j + 1];
            v.z = acc[i][j + 2] + bias[bn + tc + j + 2];
            v.w = acc[i][j + 3] + bias[bn + tc + j + 3];
            *reinterpret_cast<float4*>(Crow + j) = v;
        }
    }
}

// ----------------------------------------------------------------------------
// LIF multistep: one thread per (b, n) state; loops over T.
// charge: v = v + (h - v) * 0.5   (exact: *0.5 is power of two)
// fire:   spike = (v >= 1.0)
// reset:  hard reset to 0
// ----------------------------------------------------------------------------
__global__ __launch_bounds__(256) void lif_kernel(
    const float* __restrict__ h,
    float* __restrict__ s)
{
    const int idx = blockIdx.x * blockDim.x + threadIdx.x;  // over B*N
    const int stride = B_DIM * N_DIM;
    if (idx >= stride) return;

    float v = 0.0f;
    #pragma unroll
    for (int t = 0; t < T_DIM; t++) {
        float ht = h[(size_t)t * stride + idx];
        v = v + (ht - v) * 0.5f;
        bool fired = (v >= 1.0f);
        s[(size_t)t * stride + idx] = fired ? 1.0f : 0.0f;
        if (fired) v = 0.0f;
    }
}

// ----------------------------------------------------------------------------
// Launch
// ----------------------------------------------------------------------------
extern "C" void kernel_launch(void* const* d_in, const int* in_sizes, int n_in,
                              void* d_out, int out_size)
{
    const float* x  = (const float*)d_in[0];
    const float* w1 = (const float*)d_in[1];
    const float* b1 = (const float*)d_in[2];
    const float* w2 = (const float*)d_in[3];
    const float* b2 = (const float*)d_in[4];
    float* out = (float*)d_out;

    float* h_ptr = nullptr;
    float* s_ptr = nullptr;
    cudaGetSymbolAddress((void**)&h_ptr, g_h);
    cudaGetSymbolAddress((void**)&s_ptr, g_s);

    dim3 grid(N_DIM / BN, M_DIM / BM);   // (4, 512)
    dim3 block(256);

    // fc1: h = x @ w1^T + b1
    sgemm_nt<<<grid, block>>>(x, w1, b1, h_ptr);

    // LIF scan over T
    lif_kernel<<<(B_DIM * N_DIM) / 256, 256>>>(h_ptr, s_ptr);

    // fc2: out = s @ w2^T + b2
    sgemm_nt<<<grid, block>>>(s_ptr, w2, b2, out);
}